// round 6
// baseline (speedup 1.0000x reference)
#include <cuda_runtime.h>
#include <math.h>

#define B_   256
#define C_   512
#define L_   2048
#define HID  32
#define FL   8

// Scratch (no allocations allowed). Counters self-reset each run -> graph-replay safe.
__device__ float g_stat[B_ * C_];       // 512 KB
__device__ float g_loss[B_];            // per-sample ortho loss
__device__ int   g_samp_cnt[B_];        // blocks completed per sample (0..64)
__device__ int   g_done_cnt;            // samples completed (0..256)

// ---------------------------------------------------------------------------
// Single fused kernel.
// 16384 blocks x 256 threads. Each warp max-reduces one (b,c) row of 2048
// floats (float4 streaming loads on x only). Each block covers 8 consecutive
// rows, all inside one sample (8 | 512). Last block per sample runs the MLP;
// last sample overall runs the final loss reduction.
// NOTE: phase 2/3 use scalar loads only — no wide-access alignment hazards.
// ---------------------------------------------------------------------------
__global__ void __launch_bounds__(256) dywan_fused_kernel(
    const float* __restrict__ x,
    const float* __restrict__ W1, const float* __restrict__ b1,
    const float* __restrict__ W2, const float* __restrict__ b2,
    const float* __restrict__ W3, const float* __restrict__ b3,
    float* __restrict__ out)
{
    __shared__ float s[C_];
    __shared__ float h1[HID];
    __shared__ float h2[HID];
    __shared__ float f[2 * FL];
    __shared__ int   s_last;
    __shared__ int   s_final;

    const int warp = threadIdx.x >> 5;
    const int lane = threadIdx.x & 31;
    const int row  = blockIdx.x * 8 + warp;
    const int b    = blockIdx.x >> 6;          // 64 blocks per sample

    // ---- Phase 1: row max (HBM-bound) ----
    const float4* p = reinterpret_cast<const float4*>(x + (size_t)row * L_);
    float m = -INFINITY;
#pragma unroll
    for (int i = 0; i < 16; ++i) {
        float4 v = __ldcs(&p[lane + 32 * i]);
        m = fmaxf(m, fmaxf(fmaxf(v.x, v.y), fmaxf(v.z, v.w)));
    }
#pragma unroll
    for (int o = 16; o > 0; o >>= 1)
        m = fmaxf(m, __shfl_xor_sync(0xFFFFFFFFu, m, o));

    if (lane == 0) {
        g_stat[row] = m;
        __threadfence();                        // release this warp's stat
    }
    __syncthreads();

    // ---- Phase 2: last block of this sample runs the MLP ----
    if (threadIdx.x == 0)
        s_last = (atomicAdd(&g_samp_cnt[b], 1) == 63) ? 1 : 0;
    __syncthreads();
    if (!s_last) return;

    const int t = threadIdx.x;
    if (t == 0) g_samp_cnt[b] = 0;              // self-reset for graph replay

    if (t < 32) {
        __threadfence();                        // acquire: order after counter obs

        // Load stat row into shared (scalar, coalesced: 16 iterations x 32 lanes)
        const float* sp = g_stat + (size_t)b * C_;
#pragma unroll
        for (int i = 0; i < 16; ++i) s[t + 32 * i] = sp[t + 32 * i];
        __syncwarp();

        // Layer 1: h1 = relu(W1 @ s + b1), 4 accumulator chains
        {
            const float* w = W1 + (size_t)t * C_;
            float a0 = b1[t], a1 = 0.f, a2 = 0.f, a3 = 0.f;
#pragma unroll 4
            for (int c = 0; c < C_; c += 4) {
                a0 = fmaf(w[c + 0], s[c + 0], a0);
                a1 = fmaf(w[c + 1], s[c + 1], a1);
                a2 = fmaf(w[c + 2], s[c + 2], a2);
                a3 = fmaf(w[c + 3], s[c + 3], a3);
            }
            h1[t] = fmaxf((a0 + a1) + (a2 + a3), 0.0f);
        }
        __syncwarp();

        // Layer 2
        {
            float a = b2[t];
            const float* w = W2 + t * HID;
#pragma unroll
            for (int k = 0; k < HID; ++k) a = fmaf(w[k], h1[k], a);
            h2[t] = fmaxf(a, 0.0f);
        }
        __syncwarp();

        // Layer 3: 16 filter outputs
        if (t < 2 * FL) {
            float a = b3[t];
            const float* w = W3 + t * HID;
#pragma unroll
            for (int k = 0; k < HID; ++k) a = fmaf(w[k], h2[k], a);
            f[t] = a;
            if (t < FL) out[(size_t)b * FL + t] = a;                          // lo
            else        out[(size_t)B_ * FL + (size_t)b * FL + (t - FL)] = a; // hi
        }
        __syncwarp();

        // Per-sample ortho loss (lane 0)
        if (t == 0) {
            float lo[FL], hi[FL];
            float nl = 0.0f, nh = 0.0f;
#pragma unroll
            for (int i = 0; i < FL; ++i) {
                lo[i] = f[i]; hi[i] = f[FL + i];
                nl += lo[i] * lo[i];
                nh += hi[i] * hi[i];
            }
            const float il = 1.0f / sqrtf(nl);
            const float ih = 1.0f / sqrtf(nh);
            float Ln[FL], Hn[FL];
#pragma unroll
            for (int i = 0; i < FL; ++i) { Ln[i] = lo[i] * il; Hn[i] = hi[i] * ih; }

            float acc = 0.0f;
#pragma unroll
            for (int sft = 1; sft < FL; sft += 2) {   // shifts 1,3,5,7
                float d = 0.0f;
#pragma unroll
                for (int i = 0; i < FL; ++i) d += Ln[i] * Ln[(i - sft + FL) & (FL - 1)];
                acc += fabsf(d);
            }
            float dlh = 0.0f, dll = 0.0f, dhh = 0.0f;
#pragma unroll
            for (int i = 0; i < FL; ++i) {
                dlh += Ln[i] * Hn[i];
                dll += Ln[i] * Ln[i];
                dhh += Hn[i] * Hn[i];
            }
            acc += fabsf(dlh) + fabsf(dll - 1.0f) + fabsf(dhh - 1.0f);
            g_loss[b] = acc;
            __threadfence();                    // release per-sample loss
        }
    }
    __syncthreads();

    // ---- Phase 3: last sample overall does the final loss reduction ----
    if (threadIdx.x == 0)
        s_final = (atomicAdd(&g_done_cnt, 1) == B_ - 1) ? 1 : 0;
    __syncthreads();
    if (!s_final) return;

    if (threadIdx.x == 0) g_done_cnt = 0;       // self-reset for graph replay

    if (threadIdx.x < 32) {
        const int t2 = threadIdx.x;
        __threadfence();                        // acquire before reading g_loss
        // deterministic: fixed per-lane serial sum then fixed shuffle tree
        float a = 0.0f;
#pragma unroll
        for (int i = 0; i < 8; ++i) a += g_loss[t2 * 8 + i];
#pragma unroll
        for (int o = 16; o > 0; o >>= 1)
            a += __shfl_xor_sync(0xFFFFFFFFu, a, o);
        if (t2 == 0) out[2 * B_ * FL] = a * (1.0f / (float)B_);
    }
}

// ---------------------------------------------------------------------------
extern "C" void kernel_launch(void* const* d_in, const int* in_sizes, int n_in,
                              void* d_out, int out_size)
{
    const float* x  = (const float*)d_in[0];
    const float* W1 = (const float*)d_in[1];
    const float* b1 = (const float*)d_in[2];
    const float* W2 = (const float*)d_in[3];
    const float* b2 = (const float*)d_in[4];
    const float* W3 = (const float*)d_in[5];
    const float* b3 = (const float*)d_in[6];
    float* out = (float*)d_out;

    dywan_fused_kernel<<<(B_ * C_) / 8, 256>>>(x, W1, b1, W2, b2, W3, b3, out);
}

// round 7
// speedup vs baseline: 1.0965x; 1.0965x over previous
#include <cuda_runtime.h>
#include <math.h>

#define B_   256
#define C_   512
#define L_   2048
#define HID  32
#define FL   8

// Scratch (no allocations). Counter self-resets each run -> graph-replay safe.
__device__ float g_loss[B_];        // per-sample ortho loss
__device__ int   g_done_cnt;        // samples completed (0..256)

// ---------------------------------------------------------------------------
// One block per sample: 256 blocks x 1024 threads (32 warps).
// Each warp max-reduces 16 rows of 2048 floats -> shared stat[512].
// After one __syncthreads, warp 0 runs the whole MLP + per-sample loss from
// shared memory (no global fences on the hot path). The last block to finish
// does the deterministic 256-way loss reduction (one fence+atomic per block,
// amortized over 4 MiB of streaming -> negligible).
// ---------------------------------------------------------------------------
__global__ void __launch_bounds__(1024) dywan_fused_kernel(
    const float* __restrict__ x,
    const float* __restrict__ W1, const float* __restrict__ b1,
    const float* __restrict__ W2, const float* __restrict__ b2,
    const float* __restrict__ W3, const float* __restrict__ b3,
    float* __restrict__ out)
{
    __shared__ float s[C_];          // per-sample stats
    __shared__ float h1[HID];
    __shared__ float h2[HID];
    __shared__ float f[2 * FL];
    __shared__ int   s_final;

    const int b    = blockIdx.x;             // sample
    const int warp = threadIdx.x >> 5;       // 0..31
    const int lane = threadIdx.x & 31;

    // ---- Phase 1: 16 row-maxes per warp (HBM-bound, 4 MiB per block) ----
    const float* xb = x + (size_t)b * C_ * L_;
#pragma unroll 1
    for (int r = 0; r < 16; ++r) {
        const int row = warp * 16 + r;       // channel index within sample
        const float4* p = reinterpret_cast<const float4*>(xb + (size_t)row * L_);
        float m = -INFINITY;
#pragma unroll
        for (int i = 0; i < 16; ++i) {
            float4 v = p[lane + 32 * i];
            m = fmaxf(m, fmaxf(fmaxf(v.x, v.y), fmaxf(v.z, v.w)));
        }
#pragma unroll
        for (int o = 16; o > 0; o >>= 1)
            m = fmaxf(m, __shfl_xor_sync(0xFFFFFFFFu, m, o));
        if (lane == 0) s[row] = m;
    }
    __syncthreads();

    // ---- Phase 2: warp 0 runs the MLP for this sample (all from shared) ----
    if (warp == 0) {
        const int t = lane;                  // 0..31

        // Layer 1: h1 = relu(W1 @ s + b1), 4 accumulator chains
        {
            const float* w = W1 + (size_t)t * C_;
            float a0 = b1[t], a1 = 0.f, a2 = 0.f, a3 = 0.f;
#pragma unroll 4
            for (int c = 0; c < C_; c += 4) {
                a0 = fmaf(w[c + 0], s[c + 0], a0);
                a1 = fmaf(w[c + 1], s[c + 1], a1);
                a2 = fmaf(w[c + 2], s[c + 2], a2);
                a3 = fmaf(w[c + 3], s[c + 3], a3);
            }
            h1[t] = fmaxf((a0 + a1) + (a2 + a3), 0.0f);
        }
        __syncwarp();

        // Layer 2
        {
            float a = b2[t];
            const float* w = W2 + t * HID;
#pragma unroll
            for (int k = 0; k < HID; ++k) a = fmaf(w[k], h1[k], a);
            h2[t] = fmaxf(a, 0.0f);
        }
        __syncwarp();

        // Layer 3: 16 filter outputs
        if (t < 2 * FL) {
            float a = b3[t];
            const float* w = W3 + t * HID;
#pragma unroll
            for (int k = 0; k < HID; ++k) a = fmaf(w[k], h2[k], a);
            f[t] = a;
            if (t < FL) out[(size_t)b * FL + t] = a;                          // lo
            else        out[(size_t)B_ * FL + (size_t)b * FL + (t - FL)] = a; // hi
        }
        __syncwarp();

        // Per-sample ortho loss (lane 0)
        if (t == 0) {
            float lo[FL], hi[FL];
            float nl = 0.0f, nh = 0.0f;
#pragma unroll
            for (int i = 0; i < FL; ++i) {
                lo[i] = f[i]; hi[i] = f[FL + i];
                nl += lo[i] * lo[i];
                nh += hi[i] * hi[i];
            }
            const float il = 1.0f / sqrtf(nl);
            const float ih = 1.0f / sqrtf(nh);
            float Ln[FL], Hn[FL];
#pragma unroll
            for (int i = 0; i < FL; ++i) { Ln[i] = lo[i] * il; Hn[i] = hi[i] * ih; }

            float acc = 0.0f;
#pragma unroll
            for (int sft = 1; sft < FL; sft += 2) {   // shifts 1,3,5,7
                float d = 0.0f;
#pragma unroll
                for (int i = 0; i < FL; ++i) d += Ln[i] * Ln[(i - sft + FL) & (FL - 1)];
                acc += fabsf(d);
            }
            float dlh = 0.0f, dll = 0.0f, dhh = 0.0f;
#pragma unroll
            for (int i = 0; i < FL; ++i) {
                dlh += Ln[i] * Hn[i];
                dll += Ln[i] * Ln[i];
                dhh += Hn[i] * Hn[i];
            }
            acc += fabsf(dlh) + fabsf(dll - 1.0f) + fabsf(dhh - 1.0f);
            g_loss[b] = acc;
        }
    }
    __syncthreads();

    // ---- Phase 3: last block overall reduces the 256 losses ----
    if (threadIdx.x == 0) {
        __threadfence();                     // publish g_loss[b] (classic pattern)
        s_final = (atomicAdd(&g_done_cnt, 1) == B_ - 1) ? 1 : 0;
    }
    __syncthreads();
    if (!s_final) return;

    if (threadIdx.x == 0) g_done_cnt = 0;    // self-reset for graph replay

    if (threadIdx.x < 32) {
        const int t2 = threadIdx.x;
        __threadfence();                     // acquire before reading g_loss
        // deterministic: fixed per-lane serial sum then fixed shuffle tree
        float a = 0.0f;
#pragma unroll
        for (int i = 0; i < 8; ++i) a += g_loss[t2 * 8 + i];
#pragma unroll
        for (int o = 16; o > 0; o >>= 1)
            a += __shfl_xor_sync(0xFFFFFFFFu, a, o);
        if (t2 == 0) out[2 * B_ * FL] = a * (1.0f / (float)B_);
    }
}

// ---------------------------------------------------------------------------
extern "C" void kernel_launch(void* const* d_in, const int* in_sizes, int n_in,
                              void* d_out, int out_size)
{
    const float* x  = (const float*)d_in[0];
    const float* W1 = (const float*)d_in[1];
    const float* b1 = (const float*)d_in[2];
    const float* W2 = (const float*)d_in[3];
    const float* b2 = (const float*)d_in[4];
    const float* W3 = (const float*)d_in[5];
    const float* b3 = (const float*)d_in[6];
    float* out = (float*)d_out;

    dywan_fused_kernel<<<B_, 1024>>>(x, W1, b1, W2, b2, W3, b3, out);
}